// round 15
// baseline (speedup 1.0000x reference)
#include <cuda_runtime.h>
#include <math.h>
#include <stdint.h>

#define Bsz    4
#define Cseq   1024
#define TOK    4096
#define INDIM  128
#define DMODEL 256
#define DINNER 512
#define DSTATE 16
#define EPSV   1e-5f

#define EP_NONE 0
#define EP_BIAS 1
#define EP_SILU 2

// ---------------- scratch ----------------
#define OFF_SC   0u
#define OFF_SSM  524288u
#define OFF_WG   1572864u
#define OFF_U    2621440u
#define OFF_XZ   4718592u
#define OFF_XX   13107200u
#define OFF_DBL  17301504u
#define OFF_G    17694720u
#define OFF_MO   21889024u
#define OFF_RES  23986176u
#define SCRATCH_FLOATS 26083328u

__device__ float g_scratch[SCRATCH_FLOATS];

// ---------------- top rmsnorm row-scale ----------------
__global__ void scnorm_kernel(const float* __restrict__ x, float* __restrict__ sc)
{
    const int row = blockIdx.x * 8 + (threadIdx.x >> 5);
    const int l = threadIdx.x & 31;
    float4 v = *(const float4*)(x + (size_t)row * 128 + l * 4);
    float s = v.x * v.x + v.y * v.y + v.z * v.z + v.w * v.w;
    #pragma unroll
    for (int o = 16; o > 0; o >>= 1) s += __shfl_xor_sync(0xffffffffu, s, o);
    if (l == 0) sc[row] = rsqrtf(s * (1.f / 128.f) + EPSV);
}

// ---------------- postnorm pair (DIM=256, + add) ----------------
__global__ void rmsnorm_pair_kernel(const float* __restrict__ xb,
                                    const float* __restrict__ w0, const float* __restrict__ w1,
                                    const float* __restrict__ addb, float* __restrict__ outb)
{
    const int dir = blockIdx.y;
    const float* x   = xb   + (size_t)dir * 1048576u;
    const float* add = addb + (size_t)dir * 1048576u;
    float* out       = outb + (size_t)dir * 1048576u;
    const float* w   = dir ? w1 : w0;
    const int t = blockIdx.x;
    const int i = threadIdx.x;
    float v = x[(size_t)t * 256 + i];
    float s = v * v;
    #pragma unroll
    for (int o = 16; o > 0; o >>= 1) s += __shfl_xor_sync(0xffffffffu, s, o);
    __shared__ float ws[8];
    if ((i & 31) == 0) ws[i >> 5] = s;
    __syncthreads();
    float tot = 0.f;
    #pragma unroll
    for (int q = 0; q < 8; q++) tot += ws[q];
    float sc = rsqrtf(tot * (1.f / 256.f) + EPSV);
    out[(size_t)t * 256 + i] = v * sc * w[i] + add[(size_t)t * 256 + i];
}

struct GP {
    const float* A; const float* A2; const float* A3;
    const float* W; const float* bias; const float* resid;
    const float* rowscale; const float* anorm; float* C;
};

// ---------------- mma / cp.async / ldmatrix helpers ----------------
__device__ __forceinline__ void mma_tf32(float4& d, const uint32_t* a, const uint32_t* b)
{
    asm volatile("mma.sync.aligned.m16n8k8.row.col.f32.tf32.tf32.f32 "
                 "{%0,%1,%2,%3}, {%4,%5,%6,%7}, {%8,%9}, {%0,%1,%2,%3};"
                 : "+f"(d.x), "+f"(d.y), "+f"(d.z), "+f"(d.w)
                 : "r"(a[0]), "r"(a[1]), "r"(a[2]), "r"(a[3]),
                   "r"(b[0]), "r"(b[1]));
}

__device__ __forceinline__ void cpa16(uint32_t saddr, const float* g)
{
    asm volatile("cp.async.ca.shared.global [%0], [%1], 16;" :: "r"(saddr), "l"(g));
}

__device__ __forceinline__ void ldsm4(uint32_t addr, uint32_t& r0, uint32_t& r1,
                                      uint32_t& r2, uint32_t& r3)
{
    asm volatile("ldmatrix.sync.aligned.m8n8.x4.shared.b16 {%0,%1,%2,%3}, [%4];"
                 : "=r"(r0), "=r"(r1), "=r"(r2), "=r"(r3) : "r"(addr));
}

// ---------------- TGEMM v5: 128x128 tile, warp 32x64, 3-stage cp.async, ldmatrix ----
// C[M,N] = A[M,K] @ W[N,K]^T (+bias). M%128==0, K%16==0, nChunks>=2.
// Dynamic smem: 3 stages x (A 128x20 + B 128x20) floats = 61440 bytes.
#define TG_STAGE_FLOATS (128 * 20)
__global__ void __launch_bounds__(256) tgemm_kernel(GP g0, GP g1, int N, int K, int lda,
                                                    int epil0, int epil1, int rev0, int rev1)
{
    extern __shared__ float tsm[];
    float* Asm = tsm;                          // [3][128][20]
    float* Bsm = tsm + 3 * TG_STAGE_FLOATS;    // [3][128][20]

    const GP  p    = blockIdx.z ? g1 : g0;
    const int epil = blockIdx.z ? epil1 : epil0;
    const int rev  = blockIdx.z ? rev1 : rev0;

    const int tid  = threadIdx.x;
    const int warp = tid >> 5;
    const int lane = tid & 31;
    const int warpM = warp >> 1;        // 0..3 (32 rows each)
    const int warpN = warp & 1;         // 0..1 (64 cols each)
    const int grp = lane >> 2;
    const int tig = lane & 3;

    const int rowBase = blockIdx.y * 128;
    const int colBase = blockIdx.x * 128;

    const uint32_t as_base = (uint32_t)__cvta_generic_to_shared(Asm);
    const uint32_t bs_base = (uint32_t)__cvta_generic_to_shared(Bsm);

    const int a_roff = lane & 15;
    const int a_coff = (lane >> 4) * 4;
    const int b_roff = (lane & 7) + ((lane >> 4) << 3);
    const int b_coff = ((lane >> 3) & 1) * 4;

    auto stage = [&](int sb, int c) {
        #pragma unroll
        for (int i = 0; i < 2; i++) {
            int idx = tid + i * 256;
            int row = idx >> 2, kq = idx & 3;
            int arow = rowBase + row;
            if (rev) arow ^= (Cseq - 1);
            cpa16(as_base + (uint32_t)(((sb * 128 + row) * 20 + kq * 4) * 4),
                  p.A + (size_t)arow * lda + c * 16 + kq * 4);
        }
        #pragma unroll
        for (int i = 0; i < 2; i++) {
            int idx = tid + i * 256;
            int row = idx >> 2, kq = idx & 3;
            if (colBase + row < N)
                cpa16(bs_base + (uint32_t)(((sb * 128 + row) * 20 + kq * 4) * 4),
                      p.W + (size_t)(colBase + row) * K + c * 16 + kq * 4);
        }
        asm volatile("cp.async.commit_group;" ::: "memory");
    };

    float4 acc[2][8];
    #pragma unroll
    for (int mt = 0; mt < 2; mt++)
        #pragma unroll
        for (int nt = 0; nt < 8; nt++) acc[mt][nt] = make_float4(0.f, 0.f, 0.f, 0.f);

    const int nChunks = K >> 4;
    stage(0, 0);
    stage(1, 1);

    int buf = 0;
    for (int c = 0; c < nChunks; c++) {
        asm volatile("cp.async.wait_group 1;" ::: "memory");
        __syncthreads();   // publish chunk c; retire buffer (c+2)%3
        if (c + 2 < nChunks) stage((c + 2) % 3, c + 2);

        #pragma unroll
        for (int ks = 0; ks < 2; ks++) {
            const int k0 = ks * 8;
            uint32_t a[2][4], b[8][2];
            #pragma unroll
            for (int mt = 0; mt < 2; mt++) {
                uint32_t addr = as_base + (uint32_t)((((buf * 128 + warpM * 32 + mt * 16 + a_roff) * 20)
                                                      + k0 + a_coff) * 4);
                ldsm4(addr, a[mt][0], a[mt][1], a[mt][2], a[mt][3]);
            }
            #pragma unroll
            for (int nt2 = 0; nt2 < 4; nt2++) {
                uint32_t addr = bs_base + (uint32_t)((((buf * 128 + warpN * 64 + nt2 * 16 + b_roff) * 20)
                                                      + k0 + b_coff) * 4);
                uint32_t r0, r1, r2, r3;
                ldsm4(addr, r0, r1, r2, r3);
                b[nt2 * 2 + 0][0] = r0; b[nt2 * 2 + 0][1] = r1;
                b[nt2 * 2 + 1][0] = r2; b[nt2 * 2 + 1][1] = r3;
            }
            #pragma unroll
            for (int mt = 0; mt < 2; mt++)
                #pragma unroll
                for (int nt = 0; nt < 8; nt++)
                    mma_tf32(acc[mt][nt], a[mt], b[nt]);
        }
        buf = (buf + 1) % 3;
    }

    #pragma unroll
    for (int mt = 0; mt < 2; mt++) {
        const int row0 = rowBase + warpM * 32 + mt * 16 + grp;
        #pragma unroll
        for (int nt = 0; nt < 8; nt++) {
            const int col = colBase + warpN * 64 + nt * 8 + tig * 2;
            if (col < N) {
                float2 v0 = make_float2(acc[mt][nt].x, acc[mt][nt].y);
                float2 v1 = make_float2(acc[mt][nt].z, acc[mt][nt].w);
                if (epil != EP_NONE) {
                    float2 bb = *(const float2*)(p.bias + col);
                    v0.x += bb.x; v0.y += bb.y; v1.x += bb.x; v1.y += bb.y;
                }
                *(float2*)(p.C + (size_t)row0 * N + col)       = v0;
                *(float2*)(p.C + (size_t)(row0 + 8) * N + col) = v1;
            }
        }
    }
}

// ---------------- fused A-load helper ----------
__device__ __forceinline__ void load_a8(const float* q, const float* q2, const float* q3,
                                        const float* qn, int cmb, float4& x0, float4& x1)
{
    x0 = *(const float4*)q; x1 = *(const float4*)(q + 4);
    if (cmb) {
        float4 r0 = *(const float4*)q2, r1 = *(const float4*)(q2 + 4);
        float4 s0 = *(const float4*)q3, s1 = *(const float4*)(q3 + 4);
        x0.x *= (r0.x + s0.x); x0.y *= (r0.y + s0.y); x0.z *= (r0.z + s0.z); x0.w *= (r0.w + s0.w);
        x1.x *= (r1.x + s1.x); x1.y *= (r1.y + s1.y); x1.z *= (r1.z + s1.z); x1.w *= (r1.w + s1.w);
    }
    if (qn) {
        float4 n0 = *(const float4*)qn, n1 = *(const float4*)(qn + 4);
        x0.x *= n0.x; x0.y *= n0.y; x0.z *= n0.z; x0.w *= n0.w;
        x1.x *= n1.x; x1.y *= n1.y; x1.z *= n1.z; x1.w *= n1.w;
    }
}

// ---------------- SGEMM v4 (fused epilogues) ----------
__global__ void __launch_bounds__(256) sgemm4_kernel(GP g0, GP g1,
                                                     int N, int K, int lda,
                                                     int epil0, int epil1, int rev0, int rev1,
                                                     int cmb)
{
    const GP  p    = blockIdx.z ? g1 : g0;
    const int epil = blockIdx.z ? epil1 : epil0;
    const int rev  = blockIdx.z ? rev1 : rev0;

    __shared__ float As[2][16][136];
    __shared__ float Bs[2][16][72];

    const int tid = threadIdx.x;
    const int rowBase = blockIdx.y * 128;
    const int colBase = blockIdx.x * 64;

    const int alr = tid >> 1;
    const int alk = (tid & 1) * 8;
    const int blr = tid >> 2;
    const int blk = (tid & 3) * 4;
    const int tr = tid >> 4;
    const int tc = tid & 15;

    int arow = rowBase + alr;
    if (rev) arow ^= (Cseq - 1);
    const float* Aptr = p.A + (size_t)arow * lda + alk;
    const float* A2p  = cmb ? p.A2 + (size_t)arow * lda + alk : nullptr;
    const float* A3p  = cmb ? p.A3 + (size_t)(arow ^ (Cseq - 1)) * lda + alk : nullptr;
    const float* ANp  = p.anorm ? p.anorm + alk : nullptr;
    const float* Wptr = p.W + (size_t)(colBase + blr) * K + blk;

    {
        float4 a0, a1;
        load_a8(Aptr, A2p, A3p, ANp, cmb, a0, a1);
        float4 b0 = *(const float4*)Wptr;
        As[0][alk + 0][alr] = a0.x; As[0][alk + 1][alr] = a0.y; As[0][alk + 2][alr] = a0.z; As[0][alk + 3][alr] = a0.w;
        As[0][alk + 4][alr] = a1.x; As[0][alk + 5][alr] = a1.y; As[0][alk + 6][alr] = a1.z; As[0][alk + 7][alr] = a1.w;
        Bs[0][blk + 0][blr] = b0.x; Bs[0][blk + 1][blr] = b0.y; Bs[0][blk + 2][blr] = b0.z; Bs[0][blk + 3][blr] = b0.w;
    }
    __syncthreads();

    float acc[8][4];
    #pragma unroll
    for (int i = 0; i < 8; i++)
        #pragma unroll
        for (int j = 0; j < 4; j++) acc[i][j] = 0.f;

    const int nChunks = K >> 4;
    int buf = 0;
    for (int c = 0; c < nChunks; c++) {
        float4 aN0, aN1, bN;
        const bool more = (c + 1 < nChunks);
        if (more) {
            load_a8(Aptr + (c + 1) * 16,
                    cmb ? A2p + (c + 1) * 16 : nullptr,
                    cmb ? A3p + (c + 1) * 16 : nullptr,
                    ANp ? ANp + (c + 1) * 16 : nullptr, cmb, aN0, aN1);
            bN = *(const float4*)(Wptr + (c + 1) * 16);
        }
        #pragma unroll
        for (int k = 0; k < 16; k++) {
            float4 aA = *(const float4*)(&As[buf][k][tr * 8]);
            float4 aB = *(const float4*)(&As[buf][k][tr * 8 + 4]);
            float4 b  = *(const float4*)(&Bs[buf][k][tc * 4]);
            float av[8] = {aA.x, aA.y, aA.z, aA.w, aB.x, aB.y, aB.z, aB.w};
            #pragma unroll
            for (int i = 0; i < 8; i++) {
                acc[i][0] = fmaf(av[i], b.x, acc[i][0]);
                acc[i][1] = fmaf(av[i], b.y, acc[i][1]);
                acc[i][2] = fmaf(av[i], b.z, acc[i][2]);
                acc[i][3] = fmaf(av[i], b.w, acc[i][3]);
            }
        }
        if (more) {
            const int nb = buf ^ 1;
            As[nb][alk + 0][alr] = aN0.x; As[nb][alk + 1][alr] = aN0.y; As[nb][alk + 2][alr] = aN0.z; As[nb][alk + 3][alr] = aN0.w;
            As[nb][alk + 4][alr] = aN1.x; As[nb][alk + 5][alr] = aN1.y; As[nb][alk + 6][alr] = aN1.z; As[nb][alk + 7][alr] = aN1.w;
            Bs[nb][blk + 0][blr] = bN.x;  Bs[nb][blk + 1][blr] = bN.y;  Bs[nb][blk + 2][blr] = bN.z;  Bs[nb][blk + 3][blr] = bN.w;
            __syncthreads();
            buf = nb;
        }
    }

    const int col = colBase + tc * 4;
    float4 bb;
    if (epil != EP_NONE) bb = *(const float4*)(p.bias + col);
    #pragma unroll
    for (int i = 0; i < 8; i++) {
        const int row = rowBase + tr * 8 + i;
        float4 v = make_float4(acc[i][0], acc[i][1], acc[i][2], acc[i][3]);
        if (p.rowscale) {
            const float rs = p.rowscale[row];
            v.x *= rs; v.y *= rs; v.z *= rs; v.w *= rs;
        }
        if (epil != EP_NONE) { v.x += bb.x; v.y += bb.y; v.z += bb.z; v.w += bb.w; }
        if (epil == EP_SILU) {
            v.x = v.x / (1.f + __expf(-v.x)); v.y = v.y / (1.f + __expf(-v.y));
            v.z = v.z / (1.f + __expf(-v.z)); v.w = v.w / (1.f + __expf(-v.w));
        }
        if (p.resid) {
            const float4 rr = *(const float4*)(p.resid + (size_t)row * N + col);
            v.x += rr.x; v.y += rr.y; v.z += rr.z; v.w += rr.w;
        }
        *(float4*)(p.C + (size_t)row * N + col) = v;
    }
}

// ---------------- depthwise causal conv (K=4) + bias + silu via smem tile ----------
__global__ void __launch_bounds__(256) conv_smem_kernel(const float* __restrict__ xzb,
                                                        float* __restrict__ xxb,
                                                        const float* __restrict__ cw0,
                                                        const float* __restrict__ cb0,
                                                        const float* __restrict__ cw1,
                                                        const float* __restrict__ cb1)
{
    const int dir = blockIdx.z;
    const int b   = blockIdx.y;
    const int cchunk = blockIdx.x >> 2;
    const int dg     = blockIdx.x & 3;
    const float* xz = xzb + (size_t)dir * 4194304u;
    float* out      = xxb + (size_t)dir * 2097152u;
    const float* cw = dir ? cw1 : cw0;
    const float* cb = dir ? cb1 : cb0;
    const int c0 = cchunk * 64;
    const int tid = threadIdx.x;

    __shared__ float s[67][128];
    __shared__ float swt[4][128];
    __shared__ float sb[128];

    if (tid < 128) sb[tid] = cb[dg * 128 + tid];
    {
        const int d = tid >> 1, half = tid & 1;
        float2 w2 = *(const float2*)(cw + (size_t)(dg * 128 + d) * 4 + half * 2);
        swt[half * 2 + 0][d] = w2.x;
        swt[half * 2 + 1][d] = w2.y;
    }
    #pragma unroll
    for (int it = 0; it < 9; it++) {
        int idx = tid + it * 256;
        if (idx < 67 * 32) {
            int r = idx >> 5, c4 = idx & 31;
            int gc = c0 - 3 + r;
            float4 v = make_float4(0.f, 0.f, 0.f, 0.f);
            if (gc >= 0)
                v = *(const float4*)(xz + (size_t)(b * 1024 + gc) * 1024u + dg * 128 + c4 * 4);
            *(float4*)&s[r][c4 * 4] = v;
        }
    }
    __syncthreads();
    #pragma unroll 4
    for (int j = 0; j < 32; j++) {
        int idx = tid + j * 256;
        int tt = idx >> 7;
        int dl = idx & 127;
        float v = sb[dl];
        v = fmaf(swt[0][dl], s[tt + 0][dl], v);
        v = fmaf(swt[1][dl], s[tt + 1][dl], v);
        v = fmaf(swt[2][dl], s[tt + 2][dl], v);
        v = fmaf(swt[3][dl], s[tt + 3][dl], v);
        out[(size_t)(b * 1024 + c0 + tt) * 512u + dg * 128 + dl] = v / (1.f + __expf(-v));
    }
}

// ---------------- selective scan ----------------
struct ScanArgs {
    const float* xz; const float* xx; const float* dbl; float* g;
    const float* A0; const float* A1; const float* D0; const float* D1;
    const float* dtw0; const float* dtw1; const float* dtb0; const float* dtb1;
};

__global__ void __launch_bounds__(256) scan_kernel(ScanArgs sa)
{
    const int dir = blockIdx.z;
    const int b   = blockIdx.y;
    const int dchunk = blockIdx.x;
    const float* xz  = sa.xz  + (size_t)dir * 4194304u;
    const float* xx  = sa.xx  + (size_t)dir * 2097152u;
    const float* dbl = sa.dbl + (size_t)dir * 196608u;
    float* g         = sa.g   + (size_t)dir * 2097152u;
    const float* A_log = dir ? sa.A1 : sa.A0;
    const float* Dp    = dir ? sa.D1 : sa.D0;
    const float* dtw   = dir ? sa.dtw1 : sa.dtw0;
    const float* dtb   = dir ? sa.dtb1 : sa.dtb0;

    const int tid = threadIdx.x;
    const int dl = tid >> 3;
    const int o  = tid & 7;
    const int d  = dchunk * 32 + dl;

    __shared__ float s_dbl[32][52];
    __shared__ float s_dtw[32][17];
    __shared__ float s_dtb[32];
    __shared__ float s_dt[32][36];
    __shared__ float s_xx[32][36];
    __shared__ float s_z [32][36];
    __shared__ float s_g [32][36];

    if (tid < 32) s_dtb[tid] = dtb[dchunk * 32 + tid];
    for (int i = tid; i < 512; i += 256)
        s_dtw[i >> 4][i & 15] = dtw[(size_t)(dchunk * 32 + (i >> 4)) * 16 + (i & 15)];

    float A0r = -expf(A_log[d * 16 + o * 2 + 0]);
    float A1r = -expf(A_log[d * 16 + o * 2 + 1]);
    float h0 = 0.f, h1 = 0.f;
    const float Dv = Dp[d];

    const size_t tokBase = (size_t)b * 1024u;

    for (int t0 = 0; t0 < 1024; t0 += 32) {
        __syncthreads();
        {
            int l = tid;
            int row = l / 12, c4 = l - row * 12;
            *(float4*)&s_dbl[row][c4 * 4] =
                *(const float4*)(dbl + (tokBase + t0 + row) * 48u + c4 * 4);
            l = tid + 256;
            if (l < 384) {
                row = l / 12; c4 = l - row * 12;
                *(float4*)&s_dbl[row][c4 * 4] =
                    *(const float4*)(dbl + (tokBase + t0 + row) * 48u + c4 * 4);
            }
        }
        {
            int row = tid >> 3, c4 = tid & 7;
            *(float4*)&s_xx[row][c4 * 4] =
                *(const float4*)(xx + (tokBase + t0 + row) * 512u + dchunk * 32 + c4 * 4);
            *(float4*)&s_z[row][c4 * 4] =
                *(const float4*)(xz + (tokBase + t0 + row) * 1024u + 512 + dchunk * 32 + c4 * 4);
        }
        __syncthreads();
        #pragma unroll
        for (int i = 0; i < 4; i++) {
            int idx = tid + i * 256;
            int tt = idx >> 5, d2 = idx & 31;
            float a = s_dtb[d2];
            #pragma unroll
            for (int j = 0; j < 16; j++) a = fmaf(s_dbl[tt][j], s_dtw[d2][j], a);
            s_dt[tt][d2] = (a > 20.f) ? a : log1pf(__expf(a));
        }
        __syncthreads();
        for (int tt = 0; tt < 32; tt++) {
            float dt = s_dt[tt][dl];
            float xv = s_xx[tt][dl];
            float dx = dt * xv;
            float dA0 = __expf(dt * A0r);
            float dA1 = __expf(dt * A1r);
            h0 = fmaf(dA0, h0, dx * s_dbl[tt][16 + o * 2 + 0]);
            h1 = fmaf(dA1, h1, dx * s_dbl[tt][16 + o * 2 + 1]);
            float y = fmaf(h0, s_dbl[tt][32 + o * 2 + 0], h1 * s_dbl[tt][32 + o * 2 + 1]);
            y += __shfl_xor_sync(0xffffffffu, y, 1);
            y += __shfl_xor_sync(0xffffffffu, y, 2);
            y += __shfl_xor_sync(0xffffffffu, y, 4);
            if (o == 0) {
                float zv = s_z[tt][dl];
                float yy = fmaf(xv, Dv, y);
                s_g[tt][dl] = yy * (zv / (1.f + __expf(-zv)));
            }
        }
        __syncthreads();
        {
            int row = tid >> 3, c4 = tid & 7;
            *(float4*)(g + (tokBase + t0 + row) * 512u + dchunk * 32 + c4 * 4) =
                *(float4*)&s_g[row][c4 * 4];
        }
    }
}

// ---------------- launch ----------------
extern "C" void kernel_launch(void* const* d_in, const int* in_sizes, int n_in,
                              void* d_out, int out_size)
{
    const float* x        = (const float*)d_in[0];
    const float* W_in     = (const float*)d_in[1];
    const float* b_in     = (const float*)d_in[2];
    const float* W_wp     = (const float*)d_in[3];
    const float* b_wp     = (const float*)d_in[4];
    const float* W_fp     = (const float*)d_in[5];
    const float* b_fp     = (const float*)d_in[6];
    const float* W_bp     = (const float*)d_in[7];
    const float* b_bp     = (const float*)d_in[8];
    const float* W_out    = (const float*)d_in[9];
    const float* b_out    = (const float*)d_in[10];
    const float* norm_top = (const float*)d_in[11];

    const float* f_in_w    = (const float*)d_in[12];
    const float* f_conv_w  = (const float*)d_in[13];
    const float* f_conv_b  = (const float*)d_in[14];
    const float* f_xproj_w = (const float*)d_in[15];
    const float* f_dt_w    = (const float*)d_in[16];
    const float* f_dt_b    = (const float*)d_in[17];
    const float* f_A_log   = (const float*)d_in[18];
    const float* f_D       = (const float*)d_in[19];
    const float* f_out_w   = (const float*)d_in[20];
    const float* f_norm_w  = (const float*)d_in[21];
    const float* bk_in_w    = (const float*)d_in[22];
    const float* bk_conv_w  = (const float*)d_in[23];
    const float* bk_conv_b  = (const float*)d_in[24];
    const float* bk_xproj_w = (const float*)d_in[25];
    const float* bk_dt_w    = (const float*)d_in[26];
    const float* bk_dt_b    = (const float*)d_in[27];
    const float* bk_A_log   = (const float*)d_in[28];
    const float* bk_D       = (const float*)d_in[29];
    const float* bk_out_w   = (const float*)d_in[30];
    const float* bk_norm_w  = (const float*)d_in[31];

    float* S = nullptr;
    cudaGetSymbolAddress((void**)&S, g_scratch);

    float* sc   = S + OFF_SC;
    float* ssm  = S + OFF_SSM;
    float* wgt  = S + OFF_WG;
    float* u0   = S + OFF_U;
    float* u1   = S + OFF_U + 1048576u;
    float* xzb  = S + OFF_XZ;
    float* xxb  = S + OFF_XX;
    float* dblb = S + OFF_DBL;
    float* gb   = S + OFF_G;
    float* mob  = S + OFF_MO;
    float* res0 = S + OFF_RES;
    float* res1 = S + OFF_RES + 1048576u;

    const int TG_SMEM = 6 * TG_STAGE_FLOATS * 4;   // 61440 bytes
    cudaFuncSetAttribute(tgemm_kernel, cudaFuncAttributeMaxDynamicSharedMemorySize, TG_SMEM);

    scnorm_kernel<<<512, 256>>>(x, sc);

    {
        GP p0{x, nullptr, nullptr, W_in, b_in, nullptr, sc, norm_top, ssm};
        GP p1{x, nullptr, nullptr, W_wp, b_wp, nullptr, sc, norm_top, wgt};
        sgemm4_kernel<<<dim3(4, 32, 2), 256>>>(p0, p1, 256, 128, 128, EP_BIAS, EP_SILU, 0, 0, 0);
    }
    {
        GP p0{ssm, nullptr, nullptr, W_fp, b_fp, nullptr, nullptr, nullptr, u0};
        GP p1{ssm, nullptr, nullptr, W_bp, b_bp, nullptr, nullptr, nullptr, u1};
        tgemm_kernel<<<dim3(2, 32, 2), 256, TG_SMEM>>>(p0, p1, 256, 256, 256, EP_BIAS, EP_BIAS, 0, 1);
    }
    {
        GP p0{u0, nullptr, nullptr, f_in_w,  nullptr, nullptr, nullptr, nullptr, xzb};
        GP p1{u1, nullptr, nullptr, bk_in_w, nullptr, nullptr, nullptr, nullptr, xzb + 4194304u};
        tgemm_kernel<<<dim3(8, 32, 2), 256, TG_SMEM>>>(p0, p1, 1024, 256, 256, EP_NONE, EP_NONE, 0, 0);
    }
    conv_smem_kernel<<<dim3(64, 4, 2), 256>>>(xzb, xxb, f_conv_w, f_conv_b,
                                              bk_conv_w, bk_conv_b);
    {
        GP p0{xxb,            nullptr, nullptr, f_xproj_w,  nullptr, nullptr, nullptr, nullptr, dblb};
        GP p1{xxb + 2097152u, nullptr, nullptr, bk_xproj_w, nullptr, nullptr, nullptr, nullptr, dblb + 196608u};
        tgemm_kernel<<<dim3(1, 32, 2), 256, TG_SMEM>>>(p0, p1, 48, 512, 512, EP_NONE, EP_NONE, 0, 0);
    }
    {
        ScanArgs sa;
        sa.xz = xzb; sa.xx = xxb; sa.dbl = dblb; sa.g = gb;
        sa.A0 = f_A_log; sa.A1 = bk_A_log; sa.D0 = f_D; sa.D1 = bk_D;
        sa.dtw0 = f_dt_w; sa.dtw1 = bk_dt_w; sa.dtb0 = f_dt_b; sa.dtb1 = bk_dt_b;
        scan_kernel<<<dim3(16, 4, 2), 256>>>(sa);
    }
    {
        GP p0{gb,            nullptr, nullptr, f_out_w,  nullptr, nullptr, nullptr, nullptr, mob};
        GP p1{gb + 2097152u, nullptr, nullptr, bk_out_w, nullptr, nullptr, nullptr, nullptr, mob + 1048576u};
        tgemm_kernel<<<dim3(2, 32, 2), 256, TG_SMEM>>>(p0, p1, 256, 512, 512, EP_NONE, EP_NONE, 0, 0);
    }
    rmsnorm_pair_kernel<<<dim3(TOK, 2), 256>>>(mob, f_norm_w, bk_norm_w, u0, res0);

    {
        GP p0{wgt, res0, res1, W_out, b_out, x, nullptr, nullptr, (float*)d_out};
        sgemm4_kernel<<<dim3(2, 32, 1), 256>>>(p0, p0, 128, 256, 256, EP_BIAS, EP_BIAS, 0, 0, 1);
    }
}

// round 17
// speedup vs baseline: 1.0898x; 1.0898x over previous
#include <cuda_runtime.h>
#include <math.h>
#include <stdint.h>

#define Bsz    4
#define Cseq   1024
#define TOK    4096
#define INDIM  128
#define DMODEL 256
#define DINNER 512
#define DSTATE 16
#define EPSV   1e-5f

#define EP_NONE 0
#define EP_BIAS 1
#define EP_SILU 2

// ---------------- scratch ----------------
#define OFF_SC   0u
#define OFF_SSM  524288u      // also reused as comb buffer late in the pipeline
#define OFF_WG   1572864u
#define OFF_U    2621440u
#define OFF_XZ   4718592u
#define OFF_XX   13107200u
#define OFF_DBL  17301504u
#define OFF_G    17694720u
#define OFF_MO   21889024u
#define OFF_RES  23986176u
#define OFF_WN   26083328u    // 2 x 32768 pre-scaled weights
#define SCRATCH_FLOATS 26148864u

__device__ float g_scratch[SCRATCH_FLOATS];

// ---------------- top rmsnorm row-scale ----------------
__global__ void scnorm_kernel(const float* __restrict__ x, float* __restrict__ sc)
{
    const int row = blockIdx.x * 8 + (threadIdx.x >> 5);
    const int l = threadIdx.x & 31;
    float4 v = *(const float4*)(x + (size_t)row * 128 + l * 4);
    float s = v.x * v.x + v.y * v.y + v.z * v.z + v.w * v.w;
    #pragma unroll
    for (int o = 16; o > 0; o >>= 1) s += __shfl_xor_sync(0xffffffffu, s, o);
    if (l == 0) sc[row] = rsqrtf(s * (1.f / 128.f) + EPSV);
}

// ---------------- weight pre-scale: Wn[n,k] = W[n,k] * nw[k]  (K=128, N=256, x2) ----
__global__ void wprep_kernel(const float* __restrict__ W_in, const float* __restrict__ W_wp,
                             const float* __restrict__ nw, float* __restrict__ Wn)
{
    int gid = blockIdx.x * 256 + threadIdx.x;   // 0..65535
    int k = gid & 127;
    float w = nw[k];
    Wn[gid]          = W_in[gid & 32767] * w * (gid < 32768 ? 1.f : 0.f)
                     + (gid >= 32768 ? W_wp[gid & 32767] * w : 0.f);
}

// ---------------- postnorm pair (DIM=256, + add) ----------------
__global__ void rmsnorm_pair_kernel(const float* __restrict__ xb,
                                    const float* __restrict__ w0, const float* __restrict__ w1,
                                    const float* __restrict__ addb, float* __restrict__ outb)
{
    const int dir = blockIdx.y;
    const float* x   = xb   + (size_t)dir * 1048576u;
    const float* add = addb + (size_t)dir * 1048576u;
    float* out       = outb + (size_t)dir * 1048576u;
    const float* w   = dir ? w1 : w0;
    const int t = blockIdx.x;
    const int i = threadIdx.x;
    float v = x[(size_t)t * 256 + i];
    float s = v * v;
    #pragma unroll
    for (int o = 16; o > 0; o >>= 1) s += __shfl_xor_sync(0xffffffffu, s, o);
    __shared__ float ws[8];
    if ((i & 31) == 0) ws[i >> 5] = s;
    __syncthreads();
    float tot = 0.f;
    #pragma unroll
    for (int q = 0; q < 8; q++) tot += ws[q];
    float sc = rsqrtf(tot * (1.f / 256.f) + EPSV);
    out[(size_t)t * 256 + i] = v * sc * w[i] + add[(size_t)t * 256 + i];
}

// ---------------- combine: comb = wgt * (res0 + reverse_time(res1)) ----------------
__global__ void combine_kernel(const float* __restrict__ wg, const float* __restrict__ rf,
                               const float* __restrict__ rb, float* __restrict__ out)
{
    int gid = blockIdx.x * blockDim.x + threadIdx.x;   // TOK*256
    int n = gid & 255;
    int tok = gid >> 8;
    int rtok = tok ^ (Cseq - 1);
    out[gid] = wg[gid] * (rf[gid] + rb[((size_t)rtok << 8) + n]);
}

struct GP {
    const float* A; const float* W; const float* bias; const float* resid;
    const float* rowscale; float* C;
};

// ---------------- mma / cp.async / ldmatrix helpers ----------------
__device__ __forceinline__ void mma_tf32(float4& d, const uint32_t* a, const uint32_t* b)
{
    asm volatile("mma.sync.aligned.m16n8k8.row.col.f32.tf32.tf32.f32 "
                 "{%0,%1,%2,%3}, {%4,%5,%6,%7}, {%8,%9}, {%0,%1,%2,%3};"
                 : "+f"(d.x), "+f"(d.y), "+f"(d.z), "+f"(d.w)
                 : "r"(a[0]), "r"(a[1]), "r"(a[2]), "r"(a[3]),
                   "r"(b[0]), "r"(b[1]));
}

__device__ __forceinline__ void cpa16(uint32_t saddr, const float* g)
{
    asm volatile("cp.async.ca.shared.global [%0], [%1], 16;" :: "r"(saddr), "l"(g));
}

__device__ __forceinline__ void ldsm4(uint32_t addr, uint32_t& r0, uint32_t& r1,
                                      uint32_t& r2, uint32_t& r3)
{
    asm volatile("ldmatrix.sync.aligned.m8n8.x4.shared.b16 {%0,%1,%2,%3}, [%4];"
                 : "=r"(r0), "=r"(r1), "=r"(r2), "=r"(r3) : "r"(addr));
}

// ---------------- TGEMM64: 128x64 tile, warp 32x32, 3-stage cp.async, ldmatrix ------
// General epilogue: rowscale, bias, silu, resid. M%128==0, K%16==0, nChunks>=2.
__global__ void __launch_bounds__(256) tgemm64_kernel(GP g0, GP g1, int N, int K, int lda,
                                                      int epil0, int epil1, int rev0, int rev1)
{
    const GP  p    = blockIdx.z ? g1 : g0;
    const int epil = blockIdx.z ? epil1 : epil0;
    const int rev  = blockIdx.z ? rev1 : rev0;

    __shared__ float As[3][128][20];
    __shared__ float Bs[3][64][20];

    const int tid  = threadIdx.x;
    const int warp = tid >> 5;
    const int lane = tid & 31;
    const int warpM = warp >> 1;
    const int warpN = warp & 1;
    const int grp = lane >> 2;
    const int tig = lane & 3;

    const int rowBase = blockIdx.y * 128;
    const int colBase = blockIdx.x * 64;

    const uint32_t as_base = (uint32_t)__cvta_generic_to_shared(&As[0][0][0]);
    const uint32_t bs_base = (uint32_t)__cvta_generic_to_shared(&Bs[0][0][0]);

    const int a_roff = lane & 15;
    const int a_coff = (lane >> 4) * 4;
    const int b_roff = (lane & 7) + ((lane >> 4) << 3);
    const int b_coff = ((lane >> 3) & 1) * 4;

    auto stage = [&](int sb, int c) {
        #pragma unroll
        for (int i = 0; i < 2; i++) {
            int idx = tid + i * 256;
            int row = idx >> 2, kq = idx & 3;
            int arow = rowBase + row;
            if (rev) arow ^= (Cseq - 1);
            cpa16(as_base + (uint32_t)(((sb * 128 + row) * 20 + kq * 4) * 4),
                  p.A + (size_t)arow * lda + c * 16 + kq * 4);
        }
        {
            int row = tid >> 2, kq = tid & 3;
            if (colBase + row < N)
                cpa16(bs_base + (uint32_t)(((sb * 64 + row) * 20 + kq * 4) * 4),
                      p.W + (size_t)(colBase + row) * K + c * 16 + kq * 4);
        }
        asm volatile("cp.async.commit_group;" ::: "memory");
    };

    float4 acc[2][4];
    #pragma unroll
    for (int mt = 0; mt < 2; mt++)
        #pragma unroll
        for (int nt = 0; nt < 4; nt++) acc[mt][nt] = make_float4(0.f, 0.f, 0.f, 0.f);

    const int nChunks = K >> 4;
    stage(0, 0);
    stage(1, 1);

    int buf = 0;
    for (int c = 0; c < nChunks; c++) {
        asm volatile("cp.async.wait_group 1;" ::: "memory");
        __syncthreads();
        if (c + 2 < nChunks) stage((c + 2) % 3, c + 2);

        #pragma unroll
        for (int ks = 0; ks < 2; ks++) {
            const int k0 = ks * 8;
            uint32_t a[2][4], b[4][2];
            #pragma unroll
            for (int mt = 0; mt < 2; mt++) {
                uint32_t addr = as_base + (uint32_t)((((buf * 128 + warpM * 32 + mt * 16 + a_roff) * 20)
                                                      + k0 + a_coff) * 4);
                ldsm4(addr, a[mt][0], a[mt][1], a[mt][2], a[mt][3]);
            }
            #pragma unroll
            for (int nt2 = 0; nt2 < 2; nt2++) {
                uint32_t addr = bs_base + (uint32_t)((((buf * 64 + warpN * 32 + nt2 * 16 + b_roff) * 20)
                                                      + k0 + b_coff) * 4);
                uint32_t r0, r1, r2, r3;
                ldsm4(addr, r0, r1, r2, r3);
                b[nt2 * 2 + 0][0] = r0; b[nt2 * 2 + 0][1] = r1;
                b[nt2 * 2 + 1][0] = r2; b[nt2 * 2 + 1][1] = r3;
            }
            #pragma unroll
            for (int mt = 0; mt < 2; mt++)
                #pragma unroll
                for (int nt = 0; nt < 4; nt++)
                    mma_tf32(acc[mt][nt], a[mt], b[nt]);
        }
        buf = (buf + 1) % 3;
    }

    #pragma unroll
    for (int mt = 0; mt < 2; mt++) {
        const int row0 = rowBase + warpM * 32 + mt * 16 + grp;
        const int row1 = row0 + 8;
        float rs0 = 1.f, rs1 = 1.f;
        if (p.rowscale) { rs0 = p.rowscale[row0]; rs1 = p.rowscale[row1]; }
        #pragma unroll
        for (int nt = 0; nt < 4; nt++) {
            const int col = colBase + warpN * 32 + nt * 8 + tig * 2;
            if (col < N) {
                float2 v0 = make_float2(acc[mt][nt].x * rs0, acc[mt][nt].y * rs0);
                float2 v1 = make_float2(acc[mt][nt].z * rs1, acc[mt][nt].w * rs1);
                if (epil != EP_NONE) {
                    float2 bb = *(const float2*)(p.bias + col);
                    v0.x += bb.x; v0.y += bb.y; v1.x += bb.x; v1.y += bb.y;
                }
                if (epil == EP_SILU) {
                    v0.x = v0.x / (1.f + __expf(-v0.x)); v0.y = v0.y / (1.f + __expf(-v0.y));
                    v1.x = v1.x / (1.f + __expf(-v1.x)); v1.y = v1.y / (1.f + __expf(-v1.y));
                }
                if (p.resid) {
                    float2 r0v = *(const float2*)(p.resid + (size_t)row0 * N + col);
                    float2 r1v = *(const float2*)(p.resid + (size_t)row1 * N + col);
                    v0.x += r0v.x; v0.y += r0v.y; v1.x += r1v.x; v1.y += r1v.y;
                }
                *(float2*)(p.C + (size_t)row0 * N + col) = v0;
                *(float2*)(p.C + (size_t)row1 * N + col) = v1;
            }
        }
    }
}

// ---------------- TGEMM128: 128x128 tile, warp 32x64, 3-stage, dynamic smem ----------
// Plain epilogue (no bias). For the big xz GEMM (N=1024).
#define TG_STAGE_FLOATS (128 * 20)
__global__ void __launch_bounds__(256) tgemm128_kernel(GP g0, GP g1, int N, int K, int lda)
{
    extern __shared__ float tsm[];
    float* Asm = tsm;
    float* Bsm = tsm + 3 * TG_STAGE_FLOATS;

    const GP p = blockIdx.z ? g1 : g0;

    const int tid  = threadIdx.x;
    const int warp = tid >> 5;
    const int lane = tid & 31;
    const int warpM = warp >> 1;
    const int warpN = warp & 1;
    const int grp = lane >> 2;
    const int tig = lane & 3;

    const int rowBase = blockIdx.y * 128;
    const int colBase = blockIdx.x * 128;

    const uint32_t as_base = (uint32_t)__cvta_generic_to_shared(Asm);
    const uint32_t bs_base = (uint32_t)__cvta_generic_to_shared(Bsm);

    const int a_roff = lane & 15;
    const int a_coff = (lane >> 4) * 4;
    const int b_roff = (lane & 7) + ((lane >> 4) << 3);
    const int b_coff = ((lane >> 3) & 1) * 4;

    auto stage = [&](int sb, int c) {
        #pragma unroll
        for (int i = 0; i < 2; i++) {
            int idx = tid + i * 256;
            int row = idx >> 2, kq = idx & 3;
            cpa16(as_base + (uint32_t)(((sb * 128 + row) * 20 + kq * 4) * 4),
                  p.A + (size_t)(rowBase + row) * lda + c * 16 + kq * 4);
        }
        #pragma unroll
        for (int i = 0; i < 2; i++) {
            int idx = tid + i * 256;
            int row = idx >> 2, kq = idx & 3;
            cpa16(bs_base + (uint32_t)(((sb * 128 + row) * 20 + kq * 4) * 4),
                  p.W + (size_t)(colBase + row) * K + c * 16 + kq * 4);
        }
        asm volatile("cp.async.commit_group;" ::: "memory");
    };

    float4 acc[2][8];
    #pragma unroll
    for (int mt = 0; mt < 2; mt++)
        #pragma unroll
        for (int nt = 0; nt < 8; nt++) acc[mt][nt] = make_float4(0.f, 0.f, 0.f, 0.f);

    const int nChunks = K >> 4;
    stage(0, 0);
    stage(1, 1);

    int buf = 0;
    for (int c = 0; c < nChunks; c++) {
        asm volatile("cp.async.wait_group 1;" ::: "memory");
        __syncthreads();
        if (c + 2 < nChunks) stage((c + 2) % 3, c + 2);

        #pragma unroll
        for (int ks = 0; ks < 2; ks++) {
            const int k0 = ks * 8;
            uint32_t a[2][4], b[8][2];
            #pragma unroll
            for (int mt = 0; mt < 2; mt++) {
                uint32_t addr = as_base + (uint32_t)((((buf * 128 + warpM * 32 + mt * 16 + a_roff) * 20)
                                                      + k0 + a_coff) * 4);
                ldsm4(addr, a[mt][0], a[mt][1], a[mt][2], a[mt][3]);
            }
            #pragma unroll
            for (int nt2 = 0; nt2 < 4; nt2++) {
                uint32_t addr = bs_base + (uint32_t)((((buf * 128 + warpN * 64 + nt2 * 16 + b_roff) * 20)
                                                      + k0 + b_coff) * 4);
                uint32_t r0, r1, r2, r3;
                ldsm4(addr, r0, r1, r2, r3);
                b[nt2 * 2 + 0][0] = r0; b[nt2 * 2 + 0][1] = r1;
                b[nt2 * 2 + 1][0] = r2; b[nt2 * 2 + 1][1] = r3;
            }
            #pragma unroll
            for (int mt = 0; mt < 2; mt++)
                #pragma unroll
                for (int nt = 0; nt < 8; nt++)
                    mma_tf32(acc[mt][nt], a[mt], b[nt]);
        }
        buf = (buf + 1) % 3;
    }

    #pragma unroll
    for (int mt = 0; mt < 2; mt++) {
        const int row0 = rowBase + warpM * 32 + mt * 16 + grp;
        #pragma unroll
        for (int nt = 0; nt < 8; nt++) {
            const int col = colBase + warpN * 64 + nt * 8 + tig * 2;
            *(float2*)(p.C + (size_t)row0 * N + col)       = make_float2(acc[mt][nt].x, acc[mt][nt].y);
            *(float2*)(p.C + (size_t)(row0 + 8) * N + col) = make_float2(acc[mt][nt].z, acc[mt][nt].w);
        }
    }
}

// ---------------- depthwise causal conv (K=4) + bias + silu via smem tile ----------
__global__ void __launch_bounds__(256) conv_smem_kernel(const float* __restrict__ xzb,
                                                        float* __restrict__ xxb,
                                                        const float* __restrict__ cw0,
                                                        const float* __restrict__ cb0,
                                                        const float* __restrict__ cw1,
                                                        const float* __restrict__ cb1)
{
    const int dir = blockIdx.z;
    const int b   = blockIdx.y;
    const int cchunk = blockIdx.x >> 2;
    const int dg     = blockIdx.x & 3;
    const float* xz = xzb + (size_t)dir * 4194304u;
    float* out      = xxb + (size_t)dir * 2097152u;
    const float* cw = dir ? cw1 : cw0;
    const float* cb = dir ? cb1 : cb0;
    const int c0 = cchunk * 64;
    const int tid = threadIdx.x;

    __shared__ float s[67][128];
    __shared__ float swt[4][128];
    __shared__ float sb[128];

    if (tid < 128) sb[tid] = cb[dg * 128 + tid];
    {
        const int d = tid >> 1, half = tid & 1;
        float2 w2 = *(const float2*)(cw + (size_t)(dg * 128 + d) * 4 + half * 2);
        swt[half * 2 + 0][d] = w2.x;
        swt[half * 2 + 1][d] = w2.y;
    }
    #pragma unroll
    for (int it = 0; it < 9; it++) {
        int idx = tid + it * 256;
        if (idx < 67 * 32) {
            int r = idx >> 5, c4 = idx & 31;
            int gc = c0 - 3 + r;
            float4 v = make_float4(0.f, 0.f, 0.f, 0.f);
            if (gc >= 0)
                v = *(const float4*)(xz + (size_t)(b * 1024 + gc) * 1024u + dg * 128 + c4 * 4);
            *(float4*)&s[r][c4 * 4] = v;
        }
    }
    __syncthreads();
    #pragma unroll 4
    for (int j = 0; j < 32; j++) {
        int idx = tid + j * 256;
        int tt = idx >> 7;
        int dl = idx & 127;
        float v = sb[dl];
        v = fmaf(swt[0][dl], s[tt + 0][dl], v);
        v = fmaf(swt[1][dl], s[tt + 1][dl], v);
        v = fmaf(swt[2][dl], s[tt + 2][dl], v);
        v = fmaf(swt[3][dl], s[tt + 3][dl], v);
        out[(size_t)(b * 1024 + c0 + tt) * 512u + dg * 128 + dl] = v / (1.f + __expf(-v));
    }
}

// ---------------- selective scan ----------------
struct ScanArgs {
    const float* xz; const float* xx; const float* dbl; float* g;
    const float* A0; const float* A1; const float* D0; const float* D1;
    const float* dtw0; const float* dtw1; const float* dtb0; const float* dtb1;
};

__global__ void __launch_bounds__(256) scan_kernel(ScanArgs sa)
{
    const int dir = blockIdx.z;
    const int b   = blockIdx.y;
    const int dchunk = blockIdx.x;
    const float* xz  = sa.xz  + (size_t)dir * 4194304u;
    const float* xx  = sa.xx  + (size_t)dir * 2097152u;
    const float* dbl = sa.dbl + (size_t)dir * 196608u;
    float* g         = sa.g   + (size_t)dir * 2097152u;
    const float* A_log = dir ? sa.A1 : sa.A0;
    const float* Dp    = dir ? sa.D1 : sa.D0;
    const float* dtw   = dir ? sa.dtw1 : sa.dtw0;
    const float* dtb   = dir ? sa.dtb1 : sa.dtb0;

    const int tid = threadIdx.x;
    const int dl = tid >> 3;
    const int o  = tid & 7;
    const int d  = dchunk * 32 + dl;

    __shared__ float s_dbl[32][52];
    __shared__ float s_dtw[32][17];
    __shared__ float s_dtb[32];
    __shared__ float s_dt[32][36];
    __shared__ float s_xx[32][36];
    __shared__ float s_z [32][36];
    __shared__ float s_g [32][36];

    if (tid < 32) s_dtb[tid] = dtb[dchunk * 32 + tid];
    for (int i = tid; i < 512; i += 256)
        s_dtw[i >> 4][i & 15] = dtw[(size_t)(dchunk * 32 + (i >> 4)) * 16 + (i & 15)];

    float A0r = -expf(A_log[d * 16 + o * 2 + 0]);
    float A1r = -expf(A_log[d * 16 + o * 2 + 1]);
    float h0 = 0.f, h1 = 0.f;
    const float Dv = Dp[d];

    const size_t tokBase = (size_t)b * 1024u;

    for (int t0 = 0; t0 < 1024; t0 += 32) {
        __syncthreads();
        {
            int l = tid;
            int row = l / 12, c4 = l - row * 12;
            *(float4*)&s_dbl[row][c4 * 4] =
                *(const float4*)(dbl + (tokBase + t0 + row) * 48u + c4 * 4);
            l = tid + 256;
            if (l < 384) {
                row = l / 12; c4 = l - row * 12;
                *(float4*)&s_dbl[row][c4 * 4] =
                    *(const float4*)(dbl + (tokBase + t0 + row) * 48u + c4 * 4);
            }
        }
        {
            int row = tid >> 3, c4 = tid & 7;
            *(float4*)&s_xx[row][c4 * 4] =
                *(const float4*)(xx + (tokBase + t0 + row) * 512u + dchunk * 32 + c4 * 4);
            *(float4*)&s_z[row][c4 * 4] =
                *(const float4*)(xz + (tokBase + t0 + row) * 1024u + 512 + dchunk * 32 + c4 * 4);
        }
        __syncthreads();
        #pragma unroll
        for (int i = 0; i < 4; i++) {
            int idx = tid + i * 256;
            int tt = idx >> 5, d2 = idx & 31;
            float a = s_dtb[d2];
            #pragma unroll
            for (int j = 0; j < 16; j++) a = fmaf(s_dbl[tt][j], s_dtw[d2][j], a);
            s_dt[tt][d2] = (a > 20.f) ? a : log1pf(__expf(a));
        }
        __syncthreads();
        for (int tt = 0; tt < 32; tt++) {
            float dt = s_dt[tt][dl];
            float xv = s_xx[tt][dl];
            float dx = dt * xv;
            float dA0 = __expf(dt * A0r);
            float dA1 = __expf(dt * A1r);
            h0 = fmaf(dA0, h0, dx * s_dbl[tt][16 + o * 2 + 0]);
            h1 = fmaf(dA1, h1, dx * s_dbl[tt][16 + o * 2 + 1]);
            float y = fmaf(h0, s_dbl[tt][32 + o * 2 + 0], h1 * s_dbl[tt][32 + o * 2 + 1]);
            y += __shfl_xor_sync(0xffffffffu, y, 1);
            y += __shfl_xor_sync(0xffffffffu, y, 2);
            y += __shfl_xor_sync(0xffffffffu, y, 4);
            if (o == 0) {
                float zv = s_z[tt][dl];
                float yy = fmaf(xv, Dv, y);
                s_g[tt][dl] = yy * (zv / (1.f + __expf(-zv)));
            }
        }
        __syncthreads();
        {
            int row = tid >> 3, c4 = tid & 7;
            *(float4*)(g + (tokBase + t0 + row) * 512u + dchunk * 32 + c4 * 4) =
                *(float4*)&s_g[row][c4 * 4];
        }
    }
}

// ---------------- launch ----------------
extern "C" void kernel_launch(void* const* d_in, const int* in_sizes, int n_in,
                              void* d_out, int out_size)
{
    const float* x        = (const float*)d_in[0];
    const float* W_in     = (const float*)d_in[1];
    const float* b_in     = (const float*)d_in[2];
    const float* W_wp     = (const float*)d_in[3];
    const float* b_wp     = (const float*)d_in[4];
    const float* W_fp     = (const float*)d_in[5];
    const float* b_fp     = (const float*)d_in[6];
    const float* W_bp     = (const float*)d_in[7];
    const float* b_bp     = (const float*)d_in[8];
    const float* W_out    = (const float*)d_in[9];
    const float* b_out    = (const float*)d_in[10];
    const float* norm_top = (const float*)d_in[11];

    const float* f_in_w    = (const float*)d_in[12];
    const float* f_conv_w  = (const float*)d_in[13];
    const float* f_conv_b  = (const float*)d_in[14];
    const float* f_xproj_w = (const float*)d_in[15];
    const float* f_dt_w    = (const float*)d_in[16];
    const float* f_dt_b    = (const float*)d_in[17];
    const float* f_A_log   = (const float*)d_in[18];
    const float* f_D       = (const float*)d_in[19];
    const float* f_out_w   = (const float*)d_in[20];
    const float* f_norm_w  = (const float*)d_in[21];
    const float* bk_in_w    = (const float*)d_in[22];
    const float* bk_conv_w  = (const float*)d_in[23];
    const float* bk_conv_b  = (const float*)d_in[24];
    const float* bk_xproj_w = (const float*)d_in[25];
    const float* bk_dt_w    = (const float*)d_in[26];
    const float* bk_dt_b    = (const float*)d_in[27];
    const float* bk_A_log   = (const float*)d_in[28];
    const float* bk_D       = (const float*)d_in[29];
    const float* bk_out_w   = (const float*)d_in[30];
    const float* bk_norm_w  = (const float*)d_in[31];

    float* S = nullptr;
    cudaGetSymbolAddress((void**)&S, g_scratch);

    float* sc   = S + OFF_SC;
    float* ssm  = S + OFF_SSM;     // reused as comb later
    float* wgt  = S + OFF_WG;
    float* u0   = S + OFF_U;
    float* u1   = S + OFF_U + 1048576u;
    float* xzb  = S + OFF_XZ;
    float* xxb  = S + OFF_XX;
    float* dblb = S + OFF_DBL;
    float* gb   = S + OFF_G;
    float* mob  = S + OFF_MO;
    float* res0 = S + OFF_RES;
    float* res1 = S + OFF_RES + 1048576u;
    float* Wn_in = S + OFF_WN;
    float* Wn_wp = S + OFF_WN + 32768u;

    const int TG_SMEM = 6 * TG_STAGE_FLOATS * 4;   // 61440 bytes
    cudaFuncSetAttribute(tgemm128_kernel, cudaFuncAttributeMaxDynamicSharedMemorySize, TG_SMEM);

    scnorm_kernel<<<512, 256>>>(x, sc);
    wprep_kernel<<<256, 256>>>(W_in, W_wp, norm_top, Wn_in);

    // ssm_in & silu gate (paired), rmsnorm fused: rowscale + pre-scaled weights
    {
        GP p0{x, Wn_in, b_in, nullptr, sc, ssm};
        GP p1{x, Wn_wp, b_wp, nullptr, sc, wgt};
        tgemm64_kernel<<<dim3(4, 32, 2), 256>>>(p0, p1, 256, 128, 128, EP_BIAS, EP_SILU, 0, 0);
    }
    // fwd/bwd projections (paired; bwd reads time-reversed rows)
    {
        GP p0{ssm, W_fp, b_fp, nullptr, nullptr, u0};
        GP p1{ssm, W_bp, b_bp, nullptr, nullptr, u1};
        tgemm64_kernel<<<dim3(4, 32, 2), 256>>>(p0, p1, 256, 256, 256, EP_BIAS, EP_BIAS, 0, 1);
    }
    // xz = u @ in_w^T (both dirs) — 128-wide tile
    {
        GP p0{u0, f_in_w,  nullptr, nullptr, nullptr, xzb};
        GP p1{u1, bk_in_w, nullptr, nullptr, nullptr, xzb + 4194304u};
        tgemm128_kernel<<<dim3(8, 32, 2), 256, TG_SMEM>>>(p0, p1, 1024, 256, 256);
    }
    conv_smem_kernel<<<dim3(64, 4, 2), 256>>>(xzb, xxb, f_conv_w, f_conv_b,
                                              bk_conv_w, bk_conv_b);
    // dbl = xx @ xproj^T (both dirs), N=48
    {
        GP p0{xxb,            f_xproj_w,  nullptr, nullptr, nullptr, dblb};
        GP p1{xxb + 2097152u, bk_xproj_w, nullptr, nullptr, nullptr, dblb + 196608u};
        tgemm64_kernel<<<dim3(1, 32, 2), 256>>>(p0, p1, 48, 512, 512, EP_NONE, EP_NONE, 0, 0);
    }
    // selective scan
    {
        ScanArgs sa;
        sa.xz = xzb; sa.xx = xxb; sa.dbl = dblb; sa.g = gb;
        sa.A0 = f_A_log; sa.A1 = bk_A_log; sa.D0 = f_D; sa.D1 = bk_D;
        sa.dtw0 = f_dt_w; sa.dtw1 = bk_dt_w; sa.dtb0 = f_dt_b; sa.dtb1 = bk_dt_b;
        scan_kernel<<<dim3(16, 4, 2), 256>>>(sa);
    }
    // mamba out projection (both dirs)
    {
        GP p0{gb,            f_out_w,  nullptr, nullptr, nullptr, mob};
        GP p1{gb + 2097152u, bk_out_w, nullptr, nullptr, nullptr, mob + 1048576u};
        tgemm64_kernel<<<dim3(4, 32, 2), 256>>>(p0, p1, 256, 512, 512, EP_NONE, EP_NONE, 0, 0);
    }
    // postnorm + residual-in-mamba (both dirs)
    rmsnorm_pair_kernel<<<dim3(TOK, 2), 256>>>(mob, f_norm_w, bk_norm_w, u0, res0);

    // comb = wgt * (res0 + rev(res1))  (reuse ssm buffer)
    combine_kernel<<<(TOK * 256) / 256, 256>>>(wgt, res0, res1, ssm);
    // out = comb @ W_out^T + b_out + x
    {
        GP p0{ssm, W_out, b_out, x, nullptr, (float*)d_out};
        tgemm64_kernel<<<dim3(2, 32, 1), 256>>>(p0, p0, 128, 256, 256, EP_BIAS, EP_BIAS, 0, 0);
    }
}